// round 4
// baseline (speedup 1.0000x reference)
#include <cuda_runtime.h>
#include <cuda_bf16.h>
#include <math.h>

#define Bv 64
#define Tv 512
#define INDIM 512
#define Hv 1024
#define G4 4096   // 4*H
#define NC 1000

#define NBLK 128  // persistent blocks (<= #SMs, all co-resident)
#define NTHR 512

// ---------------- scratch (device globals: no allocations allowed) ----------
__device__ float g_xg[(size_t)Tv * Bv * G4];    // [T][B][4H]
__device__ float g_hseq[(size_t)Bv * Tv * Hv];  // [B][T][H]  (layer-0 output)
__device__ float g_h[2][Bv * Hv];               // ping-pong h
__device__ float g_c[Bv * Hv];
__device__ unsigned g_bar_cnt;                  // grid barrier state
__device__ volatile unsigned g_bar_gen;

__device__ __forceinline__ float dot4(float4 p, float4 q) {
    float s = p.x * q.x;
    s = fmaf(p.y, q.y, s);
    s = fmaf(p.z, q.z, s);
    s = fmaf(p.w, q.w, s);
    return s;
}

// software grid barrier (all NBLK blocks resident by construction)
__device__ __forceinline__ void grid_barrier() {
    __syncthreads();
    if (threadIdx.x == 0) {
        __threadfence();
        unsigned my = g_bar_gen;
        if (atomicAdd(&g_bar_cnt, 1u) == (unsigned)(gridDim.x - 1)) {
            g_bar_cnt = 0;
            __threadfence();
            g_bar_gen = my + 1;
        } else {
            while (g_bar_gen == my) { }
            __threadfence();
        }
    }
    __syncthreads();
}

// ---------------- zero h/c before each layer --------------------------------
__global__ void zero_state_kernel() {
    int i = blockIdx.x * blockDim.x + threadIdx.x;
    if (i < Bv * Hv) {
        g_h[0][i] = 0.f;
        g_h[1][i] = 0.f;
        g_c[i]    = 0.f;
    }
}

// ---------------- input-projection GEMM -------------------------------------
// C[m,n] = sum_k A[m,k]*W[n,k] + bias1[n] + bias2[n]
// m = b*T + t ; output -> g_xg[t][b][n].  A==nullptr means A = g_hseq.
__global__ __launch_bounds__(256) void gemm_xg_kernel(
    const float* __restrict__ A, const float* __restrict__ W,
    const float* __restrict__ bias1, const float* __restrict__ bias2,
    int K)
{
    const int BM = 128, BN = 64, BK = 16;
    __shared__ float As[BK][BM + 4];
    __shared__ float Bs[BK][BN + 4];

    const float* Ap = A ? A : g_hseq;

    int m0 = blockIdx.x * BM;
    int n0 = blockIdx.y * BN;
    int tid = threadIdx.x;
    int tx = tid & 15;
    int ty = tid >> 4;

    float acc[8][4];
#pragma unroll
    for (int i = 0; i < 8; i++)
#pragma unroll
        for (int j = 0; j < 4; j++) acc[i][j] = 0.f;

    for (int k0 = 0; k0 < K; k0 += BK) {
#pragma unroll
        for (int i = 0; i < 2; i++) {
            int id  = tid * 2 + i;
            int row = id >> 2;
            int kk  = (id & 3) * 4;
            float4 v = *(const float4*)(Ap + (size_t)(m0 + row) * K + k0 + kk);
            As[kk + 0][row] = v.x; As[kk + 1][row] = v.y;
            As[kk + 2][row] = v.z; As[kk + 3][row] = v.w;
        }
        {
            int row = tid >> 2;
            int kk  = (tid & 3) * 4;
            float4 v = *(const float4*)(W + (size_t)(n0 + row) * K + k0 + kk);
            Bs[kk + 0][row] = v.x; Bs[kk + 1][row] = v.y;
            Bs[kk + 2][row] = v.z; Bs[kk + 3][row] = v.w;
        }
        __syncthreads();
#pragma unroll
        for (int k = 0; k < BK; k++) {
            float a[8], bq[4];
            *(float4*)&a[0] = *(const float4*)&As[k][ty * 8];
            *(float4*)&a[4] = *(const float4*)&As[k][ty * 8 + 4];
            *(float4*)&bq[0] = *(const float4*)&Bs[k][tx * 4];
#pragma unroll
            for (int i = 0; i < 8; i++)
#pragma unroll
                for (int j = 0; j < 4; j++)
                    acc[i][j] = fmaf(a[i], bq[j], acc[i][j]);
        }
        __syncthreads();
    }

    float bb[4];
#pragma unroll
    for (int j = 0; j < 4; j++) {
        int n = n0 + tx * 4 + j;
        bb[j] = bias1[n] + bias2[n];
    }
#pragma unroll
    for (int i = 0; i < 8; i++) {
        int m = m0 + ty * 8 + i;
        int b = m >> 9;
        int t = m & 511;
        float* o = g_xg + ((size_t)t * Bv + b) * G4 + n0 + tx * 4;
        float4 v;
        v.x = acc[i][0] + bb[0]; v.y = acc[i][1] + bb[1];
        v.z = acc[i][2] + bb[2]; v.w = acc[i][3] + bb[3];
        *(float4*)o = v;
    }
}

// ---------------- persistent LSTM layer --------------------------------------
// One launch runs all Tv steps. 128 blocks x 512 threads, grid barrier between
// steps. Block owns j-tile of 8; its Whh slice (32x1024 fp32 = 128 KB) lives in
// smem for the whole layer.
//
// Thread roles (compute): tid = unit*8 + ks;  ks = k-split 0..7 (kchunk 128),
//   unit = cjj(8) x bgrp(8) -> 8 batches x 4 gates register tile.
// Reduction over ks via __shfl (8-lane segments), then 1 cell per thread for
// the pointwise update (pj = tid&7, pb = tid>>3).
#define WS_FLOATS   (32 * 1024)          // weight slice
#define HS_STRIDE   2052                 // 64*32 + 4 pad (bank offset per ks)
#define HS_FLOATS   (8 * HS_STRIDE)
#define GT_STRIDE   68                   // 64 + 4 pad
#define GT_FLOATS   (4 * 8 * GT_STRIDE)
#define SMEM_FLOATS (WS_FLOATS + HS_FLOATS + GT_FLOATS)
#define SMEM_BYTES  (SMEM_FLOATS * 4)

template <bool WRITE_SEQ>
__global__ __launch_bounds__(NTHR, 1) void lstm_layer_kernel(
    const float* __restrict__ Whh)
{
    extern __shared__ float sm[];
    float* ws    = sm;                       // [32 rows][1024 k] (k swizzled)
    float* hs    = sm + WS_FLOATS;           // [8 ks][64 b][32 k] (slice pad 4)
    float* gates = sm + WS_FLOATS + HS_FLOATS; // [4g*8jj][stride 68]

    const int tid   = threadIdx.x;
    const int j0    = blockIdx.x * 8;
    const int ks    = tid & 7;
    const int unit  = tid >> 3;          // 0..63
    const int cjj   = unit & 7;
    const int b0    = (unit >> 3) * 8;   // 0,8,..,56
    const int kbase = ks * 128;
    const int pj    = tid & 7;           // pointwise cell
    const int pb    = tid >> 3;

    // ---- load Whh slice into smem once (k-swizzled: XOR bits[2:4] with ks) --
    for (int i = tid; i < 32 * 256; i += NTHR) {
        int r  = i >> 8;              // row 0..31 : gate = r>>3, jl = r&7
        int k  = (i & 255) * 4;
        int gate = r >> 3, jl = r & 7;
        float4 v = *(const float4*)(Whh + ((size_t)(gate * Hv + j0 + jl)) * Hv + k);
        int ksw = k ^ (((k >> 7) & 7) * 4);
        *(float4*)(ws + r * 1024 + ksw) = v;
    }
    __syncthreads();

    for (int t = 0; t < Tv; t++) {
        const float* __restrict__ h_in  = g_h[t & 1];
        float* __restrict__       h_out = g_h[(t + 1) & 1];
        const float* __restrict__ xg    = g_xg + (size_t)t * Bv * G4;

        // prefetch this thread's xg gate values (hides DRAM stream)
        float xv0 = xg[pb * G4 + 0 * Hv + j0 + pj];
        float xv1 = xg[pb * G4 + 1 * Hv + j0 + pj];
        float xv2 = xg[pb * G4 + 2 * Hv + j0 + pj];
        float xv3 = xg[pb * G4 + 3 * Hv + j0 + pj];

        float acc[4][8];
#pragma unroll
        for (int g = 0; g < 4; g++)
#pragma unroll
            for (int i = 0; i < 8; i++) acc[g][i] = 0.f;

        for (int p = 0; p < 4; p++) {          // k-phases of 32 within kchunk
            // load hs: 8 slices x 64 b x 32 k = 4096 float4, 8 per thread
#pragma unroll
            for (int l = 0; l < 8; l++) {
                int b  = tid >> 3;
                int kk = (tid & 7) * 4;
                float4 v = *(const float4*)(h_in + b * Hv + l * 128 + p * 32 + kk);
                *(float4*)(hs + l * HS_STRIDE + b * 32 + kk) = v;
            }
            __syncthreads();

            const float* hsl = hs + ks * HS_STRIDE;
#pragma unroll
            for (int kk4 = 0; kk4 < 8; kk4++) {
                int kw   = kbase + p * 32 + kk4 * 4;
                int kwsw = kw ^ (ks * 4);      // (kw>>7)&7 == ks
                float4 w0 = *(const float4*)(ws + (0 * 8 + cjj) * 1024 + kwsw);
                float4 w1 = *(const float4*)(ws + (1 * 8 + cjj) * 1024 + kwsw);
                float4 w2 = *(const float4*)(ws + (2 * 8 + cjj) * 1024 + kwsw);
                float4 w3 = *(const float4*)(ws + (3 * 8 + cjj) * 1024 + kwsw);
#pragma unroll
                for (int i = 0; i < 8; i++) {
                    float4 h4 = *(const float4*)(hsl + (b0 + i) * 32 + kk4 * 4);
                    acc[0][i] += dot4(h4, w0);
                    acc[1][i] += dot4(h4, w1);
                    acc[2][i] += dot4(h4, w2);
                    acc[3][i] += dot4(h4, w3);
                }
            }
            __syncthreads();
        }

        // reduce over ks (lanes differ in low 3 bits -> 8-lane segments)
#pragma unroll
        for (int g = 0; g < 4; g++)
#pragma unroll
            for (int i = 0; i < 8; i++) {
                float v = acc[g][i];
                v += __shfl_down_sync(0xffffffffu, v, 4, 8);
                v += __shfl_down_sync(0xffffffffu, v, 2, 8);
                v += __shfl_down_sync(0xffffffffu, v, 1, 8);
                acc[g][i] = v;
            }
        if (ks == 0) {
#pragma unroll
            for (int g = 0; g < 4; g++)
#pragma unroll
                for (int i = 0; i < 8; i++)
                    gates[(g * 8 + cjj) * GT_STRIDE + b0 + i] = acc[g][i];
        }
        __syncthreads();

        // pointwise update: one (j,b) cell per thread
        {
            float pi = gates[(0 * 8 + pj) * GT_STRIDE + pb] + xv0;
            float pf = gates[(1 * 8 + pj) * GT_STRIDE + pb] + xv1;
            float pg = gates[(2 * 8 + pj) * GT_STRIDE + pb] + xv2;
            float po = gates[(3 * 8 + pj) * GT_STRIDE + pb] + xv3;
            float ig = 1.f / (1.f + expf(-pi));
            float fg = 1.f / (1.f + expf(-pf));
            float gg = tanhf(pg);
            float og = 1.f / (1.f + expf(-po));
            int ci = pb * Hv + j0 + pj;
            float c_new = fg * g_c[ci] + ig * gg;
            float h_new = og * tanhf(c_new);
            g_c[ci]   = c_new;
            h_out[ci] = h_new;
            if (WRITE_SEQ)
                g_hseq[((size_t)pb * Tv + t) * Hv + j0 + pj] = h_new;
        }
        grid_barrier();
    }
}

// ---------------- final FC ---------------------------------------------------
__global__ void fc_kernel(const float* __restrict__ fc_w,
                          const float* __restrict__ fc_b,
                          float* __restrict__ out)
{
    int idx = blockIdx.x * blockDim.x + threadIdx.x;
    if (idx >= Bv * NC) return;
    int b = idx / NC;
    int n = idx % NC;
    const float* h = &g_h[Tv & 1][b * Hv];   // state after step t=Tv-1
    const float* w = fc_w + (size_t)n * Hv;
    float s = 0.f;
#pragma unroll 4
    for (int k = 0; k < Hv; k += 4) {
        float4 hv = *(const float4*)(h + k);
        float4 wv = *(const float4*)(w + k);
        s += dot4(hv, wv);
    }
    out[idx] = s + fc_b[n];
}

// ---------------- launch -----------------------------------------------------
extern "C" void kernel_launch(void* const* d_in, const int* in_sizes, int n_in,
                              void* d_out, int out_size)
{
    const float* x     = (const float*)d_in[0];
    const float* W_ih0 = (const float*)d_in[1];
    const float* W_hh0 = (const float*)d_in[2];
    const float* b_ih0 = (const float*)d_in[3];
    const float* b_hh0 = (const float*)d_in[4];
    const float* W_ih1 = (const float*)d_in[5];
    const float* W_hh1 = (const float*)d_in[6];
    const float* b_ih1 = (const float*)d_in[7];
    const float* b_hh1 = (const float*)d_in[8];
    const float* fc_w  = (const float*)d_in[9];
    const float* fc_b  = (const float*)d_in[10];
    float* out = (float*)d_out;

    cudaFuncSetAttribute(lstm_layer_kernel<true>,
                         cudaFuncAttributeMaxDynamicSharedMemorySize, SMEM_BYTES);
    cudaFuncSetAttribute(lstm_layer_kernel<false>,
                         cudaFuncAttributeMaxDynamicSharedMemorySize, SMEM_BYTES);

    dim3 gemm_grid(Bv * Tv / 128, G4 / 64);   // (256, 64)

    // ---- layer 0 (writes g_hseq) ----
    zero_state_kernel<<<(Bv * Hv + 255) / 256, 256>>>();
    gemm_xg_kernel<<<gemm_grid, 256>>>(x, W_ih0, b_ih0, b_hh0, INDIM);
    lstm_layer_kernel<true><<<NBLK, NTHR, SMEM_BYTES>>>(W_hh0);

    // ---- layer 1 ----
    gemm_xg_kernel<<<gemm_grid, 256>>>(nullptr, W_ih1, b_ih1, b_hh1, Hv);
    zero_state_kernel<<<(Bv * Hv + 255) / 256, 256>>>();
    lstm_layer_kernel<false><<<NBLK, NTHR, SMEM_BYTES>>>(W_hh1);

    // ---- classifier ----
    fc_kernel<<<(Bv * NC + 255) / 256, 256>>>(fc_w, fc_b, out);
}

// round 5
// speedup vs baseline: 1.0013x; 1.0013x over previous
#include <cuda_runtime.h>
#include <cuda_bf16.h>
#include <math.h>

#define Bv 64
#define Tv 512
#define INDIM 512
#define Hv 1024
#define G4 4096   // 4*H
#define NC 1000

#define NBLK 128  // persistent blocks (<= #SMs, all co-resident)
#define NTHR 512

// ---------------- scratch (device globals: no allocations allowed) ----------
__device__ float g_xg[(size_t)Tv * Bv * G4];    // [T][B][4H]
__device__ float g_hseq[(size_t)Bv * Tv * Hv];  // [B][T][H]  (layer-0 output)
__device__ float g_h[2][Bv * Hv];               // ping-pong h
__device__ float g_c[Bv * Hv];
__device__ unsigned g_bar_cnt;                  // grid barrier state
__device__ volatile unsigned g_bar_gen;

__device__ __forceinline__ float dot4(float4 p, float4 q) {
    float s = p.x * q.x;
    s = fmaf(p.y, q.y, s);
    s = fmaf(p.z, q.z, s);
    s = fmaf(p.w, q.w, s);
    return s;
}

// software grid barrier (all NBLK blocks resident by construction)
__device__ __forceinline__ void grid_barrier() {
    __syncthreads();
    if (threadIdx.x == 0) {
        __threadfence();
        unsigned my = g_bar_gen;
        if (atomicAdd(&g_bar_cnt, 1u) == (unsigned)(gridDim.x - 1)) {
            g_bar_cnt = 0;
            __threadfence();
            g_bar_gen = my + 1;
        } else {
            while (g_bar_gen == my) { }
            __threadfence();
        }
    }
    __syncthreads();
}

// ---------------- zero h/c before each layer --------------------------------
__global__ void zero_state_kernel() {
    int i = blockIdx.x * blockDim.x + threadIdx.x;
    if (i < Bv * Hv) {
        g_h[0][i] = 0.f;
        g_h[1][i] = 0.f;
        g_c[i]    = 0.f;
    }
}

// ---------------- input-projection GEMM -------------------------------------
// C[m,n] = sum_k A[m,k]*W[n,k] + bias1[n] + bias2[n]
// m = b*T + t ; output -> g_xg[t][b][n].  A==nullptr means A = g_hseq.
__global__ __launch_bounds__(256) void gemm_xg_kernel(
    const float* __restrict__ A, const float* __restrict__ W,
    const float* __restrict__ bias1, const float* __restrict__ bias2,
    int K)
{
    const int BM = 128, BN = 64, BK = 16;
    __shared__ float As[BK][BM + 4];
    __shared__ float Bs[BK][BN + 4];

    const float* Ap = A ? A : g_hseq;

    int m0 = blockIdx.x * BM;
    int n0 = blockIdx.y * BN;
    int tid = threadIdx.x;
    int tx = tid & 15;
    int ty = tid >> 4;

    float acc[8][4];
#pragma unroll
    for (int i = 0; i < 8; i++)
#pragma unroll
        for (int j = 0; j < 4; j++) acc[i][j] = 0.f;

    for (int k0 = 0; k0 < K; k0 += BK) {
#pragma unroll
        for (int i = 0; i < 2; i++) {
            int id  = tid * 2 + i;
            int row = id >> 2;
            int kk  = (id & 3) * 4;
            float4 v = *(const float4*)(Ap + (size_t)(m0 + row) * K + k0 + kk);
            As[kk + 0][row] = v.x; As[kk + 1][row] = v.y;
            As[kk + 2][row] = v.z; As[kk + 3][row] = v.w;
        }
        {
            int row = tid >> 2;
            int kk  = (tid & 3) * 4;
            float4 v = *(const float4*)(W + (size_t)(n0 + row) * K + k0 + kk);
            Bs[kk + 0][row] = v.x; Bs[kk + 1][row] = v.y;
            Bs[kk + 2][row] = v.z; Bs[kk + 3][row] = v.w;
        }
        __syncthreads();
#pragma unroll
        for (int k = 0; k < BK; k++) {
            float a[8], bq[4];
            *(float4*)&a[0] = *(const float4*)&As[k][ty * 8];
            *(float4*)&a[4] = *(const float4*)&As[k][ty * 8 + 4];
            *(float4*)&bq[0] = *(const float4*)&Bs[k][tx * 4];
#pragma unroll
            for (int i = 0; i < 8; i++)
#pragma unroll
                for (int j = 0; j < 4; j++)
                    acc[i][j] = fmaf(a[i], bq[j], acc[i][j]);
        }
        __syncthreads();
    }

    float bb[4];
#pragma unroll
    for (int j = 0; j < 4; j++) {
        int n = n0 + tx * 4 + j;
        bb[j] = bias1[n] + bias2[n];
    }
#pragma unroll
    for (int i = 0; i < 8; i++) {
        int m = m0 + ty * 8 + i;
        int b = m >> 9;
        int t = m & 511;
        float* o = g_xg + ((size_t)t * Bv + b) * G4 + n0 + tx * 4;
        float4 v;
        v.x = acc[i][0] + bb[0]; v.y = acc[i][1] + bb[1];
        v.z = acc[i][2] + bb[2]; v.w = acc[i][3] + bb[3];
        *(float4*)o = v;
    }
}

// ---------------- persistent LSTM layer --------------------------------------
// One launch runs all Tv steps. 128 blocks x 512 threads, grid barrier between
// steps. Block owns j-tile of 8; its Whh slice (32x1024 fp32 = 128 KB) lives in
// smem for the whole layer.
//
// Thread roles (compute): tid = unit*8 + ks;  ks = k-split 0..7 (kchunk 128),
//   unit = cjj(8) x bgrp(8) -> 8 batches x 4 gates register tile.
// Reduction over ks via __shfl (8-lane segments), then 1 cell per thread for
// the pointwise update (pj = tid&7, pb = tid>>3).
#define WS_FLOATS   (32 * 1024)          // weight slice
#define HS_STRIDE   2052                 // 64*32 + 4 pad (bank offset per ks)
#define HS_FLOATS   (8 * HS_STRIDE)
#define GT_STRIDE   68                   // 64 + 4 pad
#define GT_FLOATS   (4 * 8 * GT_STRIDE)
#define SMEM_FLOATS (WS_FLOATS + HS_FLOATS + GT_FLOATS)
#define SMEM_BYTES  (SMEM_FLOATS * 4)

template <bool WRITE_SEQ>
__global__ __launch_bounds__(NTHR, 1) void lstm_layer_kernel(
    const float* __restrict__ Whh)
{
    extern __shared__ float sm[];
    float* ws    = sm;                       // [32 rows][1024 k] (k swizzled)
    float* hs    = sm + WS_FLOATS;           // [8 ks][64 b][32 k] (slice pad 4)
    float* gates = sm + WS_FLOATS + HS_FLOATS; // [4g*8jj][stride 68]

    const int tid   = threadIdx.x;
    const int j0    = blockIdx.x * 8;
    const int ks    = tid & 7;
    const int unit  = tid >> 3;          // 0..63
    const int cjj   = unit & 7;
    const int b0    = (unit >> 3) * 8;   // 0,8,..,56
    const int kbase = ks * 128;
    const int pj    = tid & 7;           // pointwise cell
    const int pb    = tid >> 3;

    // ---- load Whh slice into smem once (k-swizzled: XOR bits[2:4] with ks) --
    for (int i = tid; i < 32 * 256; i += NTHR) {
        int r  = i >> 8;              // row 0..31 : gate = r>>3, jl = r&7
        int k  = (i & 255) * 4;
        int gate = r >> 3, jl = r & 7;
        float4 v = *(const float4*)(Whh + ((size_t)(gate * Hv + j0 + jl)) * Hv + k);
        int ksw = k ^ (((k >> 7) & 7) * 4);
        *(float4*)(ws + r * 1024 + ksw) = v;
    }
    __syncthreads();

    for (int t = 0; t < Tv; t++) {
        const float* __restrict__ h_in  = g_h[t & 1];
        float* __restrict__       h_out = g_h[(t + 1) & 1];
        const float* __restrict__ xg    = g_xg + (size_t)t * Bv * G4;

        // prefetch this thread's xg gate values (hides DRAM stream)
        float xv0 = xg[pb * G4 + 0 * Hv + j0 + pj];
        float xv1 = xg[pb * G4 + 1 * Hv + j0 + pj];
        float xv2 = xg[pb * G4 + 2 * Hv + j0 + pj];
        float xv3 = xg[pb * G4 + 3 * Hv + j0 + pj];

        float acc[4][8];
#pragma unroll
        for (int g = 0; g < 4; g++)
#pragma unroll
            for (int i = 0; i < 8; i++) acc[g][i] = 0.f;

        for (int p = 0; p < 4; p++) {          // k-phases of 32 within kchunk
            // load hs: 8 slices x 64 b x 32 k = 4096 float4, 8 per thread
#pragma unroll
            for (int l = 0; l < 8; l++) {
                int b  = tid >> 3;
                int kk = (tid & 7) * 4;
                float4 v = *(const float4*)(h_in + b * Hv + l * 128 + p * 32 + kk);
                *(float4*)(hs + l * HS_STRIDE + b * 32 + kk) = v;
            }
            __syncthreads();

            const float* hsl = hs + ks * HS_STRIDE;
#pragma unroll
            for (int kk4 = 0; kk4 < 8; kk4++) {
                int kw   = kbase + p * 32 + kk4 * 4;
                int kwsw = kw ^ (ks * 4);      // (kw>>7)&7 == ks
                float4 w0 = *(const float4*)(ws + (0 * 8 + cjj) * 1024 + kwsw);
                float4 w1 = *(const float4*)(ws + (1 * 8 + cjj) * 1024 + kwsw);
                float4 w2 = *(const float4*)(ws + (2 * 8 + cjj) * 1024 + kwsw);
                float4 w3 = *(const float4*)(ws + (3 * 8 + cjj) * 1024 + kwsw);
#pragma unroll
                for (int i = 0; i < 8; i++) {
                    float4 h4 = *(const float4*)(hsl + (b0 + i) * 32 + kk4 * 4);
                    acc[0][i] += dot4(h4, w0);
                    acc[1][i] += dot4(h4, w1);
                    acc[2][i] += dot4(h4, w2);
                    acc[3][i] += dot4(h4, w3);
                }
            }
            __syncthreads();
        }

        // reduce over ks (lanes differ in low 3 bits -> 8-lane segments)
#pragma unroll
        for (int g = 0; g < 4; g++)
#pragma unroll
            for (int i = 0; i < 8; i++) {
                float v = acc[g][i];
                v += __shfl_down_sync(0xffffffffu, v, 4, 8);
                v += __shfl_down_sync(0xffffffffu, v, 2, 8);
                v += __shfl_down_sync(0xffffffffu, v, 1, 8);
                acc[g][i] = v;
            }
        if (ks == 0) {
#pragma unroll
            for (int g = 0; g < 4; g++)
#pragma unroll
                for (int i = 0; i < 8; i++)
                    gates[(g * 8 + cjj) * GT_STRIDE + b0 + i] = acc[g][i];
        }
        __syncthreads();

        // pointwise update: one (j,b) cell per thread
        {
            float pi = gates[(0 * 8 + pj) * GT_STRIDE + pb] + xv0;
            float pf = gates[(1 * 8 + pj) * GT_STRIDE + pb] + xv1;
            float pg = gates[(2 * 8 + pj) * GT_STRIDE + pb] + xv2;
            float po = gates[(3 * 8 + pj) * GT_STRIDE + pb] + xv3;
            float ig = 1.f / (1.f + expf(-pi));
            float fg = 1.f / (1.f + expf(-pf));
            float gg = tanhf(pg);
            float og = 1.f / (1.f + expf(-po));
            int ci = pb * Hv + j0 + pj;
            float c_new = fg * g_c[ci] + ig * gg;
            float h_new = og * tanhf(c_new);
            g_c[ci]   = c_new;
            h_out[ci] = h_new;
            if (WRITE_SEQ)
                g_hseq[((size_t)pb * Tv + t) * Hv + j0 + pj] = h_new;
        }
        grid_barrier();
    }
}

// ---------------- final FC ---------------------------------------------------
__global__ void fc_kernel(const float* __restrict__ fc_w,
                          const float* __restrict__ fc_b,
                          float* __restrict__ out)
{
    int idx = blockIdx.x * blockDim.x + threadIdx.x;
    if (idx >= Bv * NC) return;
    int b = idx / NC;
    int n = idx % NC;
    const float* h = &g_h[Tv & 1][b * Hv];   // state after step t=Tv-1
    const float* w = fc_w + (size_t)n * Hv;
    float s = 0.f;
#pragma unroll 4
    for (int k = 0; k < Hv; k += 4) {
        float4 hv = *(const float4*)(h + k);
        float4 wv = *(const float4*)(w + k);
        s += dot4(hv, wv);
    }
    out[idx] = s + fc_b[n];
}

// ---------------- launch -----------------------------------------------------
extern "C" void kernel_launch(void* const* d_in, const int* in_sizes, int n_in,
                              void* d_out, int out_size)
{
    const float* x     = (const float*)d_in[0];
    const float* W_ih0 = (const float*)d_in[1];
    const float* W_hh0 = (const float*)d_in[2];
    const float* b_ih0 = (const float*)d_in[3];
    const float* b_hh0 = (const float*)d_in[4];
    const float* W_ih1 = (const float*)d_in[5];
    const float* W_hh1 = (const float*)d_in[6];
    const float* b_ih1 = (const float*)d_in[7];
    const float* b_hh1 = (const float*)d_in[8];
    const float* fc_w  = (const float*)d_in[9];
    const float* fc_b  = (const float*)d_in[10];
    float* out = (float*)d_out;

    cudaFuncSetAttribute(lstm_layer_kernel<true>,
                         cudaFuncAttributeMaxDynamicSharedMemorySize, SMEM_BYTES);
    cudaFuncSetAttribute(lstm_layer_kernel<false>,
                         cudaFuncAttributeMaxDynamicSharedMemorySize, SMEM_BYTES);

    dim3 gemm_grid(Bv * Tv / 128, G4 / 64);   // (256, 64)

    // ---- layer 0 (writes g_hseq) ----
    zero_state_kernel<<<(Bv * Hv + 255) / 256, 256>>>();
    gemm_xg_kernel<<<gemm_grid, 256>>>(x, W_ih0, b_ih0, b_hh0, INDIM);
    lstm_layer_kernel<true><<<NBLK, NTHR, SMEM_BYTES>>>(W_hh0);

    // ---- layer 1 ----
    gemm_xg_kernel<<<gemm_grid, 256>>>(nullptr, W_ih1, b_ih1, b_hh1, Hv);
    zero_state_kernel<<<(Bv * Hv + 255) / 256, 256>>>();
    lstm_layer_kernel<false><<<NBLK, NTHR, SMEM_BYTES>>>(W_hh1);

    // ---- classifier ----
    fc_kernel<<<(Bv * NC + 255) / 256, 256>>>(fc_w, fc_b, out);
}